// round 10
// baseline (speedup 1.0000x reference)
#include <cuda_runtime.h>

// ---------------------------------------------------------------------------
// WaveConv2d: 4-level db6 DWT -> per-pixel 32x32 channel mix at coarsest level
//             -> 4-level inverse DWT.  All fp32.
//
// R9: - __launch_bounds__(256,2): keep packed f32x2 coefficients resident
//       (R8's 46-reg budget forced remat movs -> alu pipe 51%)
//     - fdwt2 stage A pre-duplicates inputs into smem ((v,v) doubles) so
//       stage B FFMA2 reads operands directly via LDS.64 (zero movs)
//     - mix kernels merged into one launch (grid.z)
// ---------------------------------------------------------------------------

#define DIV_UP(a,b) (((a)+(b)-1)/(b))

__device__ constexpr float c_lo[12] = {
   0.11154074335008017f,  0.4946238903983854f,   0.7511339080215775f,
   0.3152503517092432f,  -0.22626469396516913f, -0.12976686756709563f,
   0.09750160558707936f,  0.02752286553001629f, -0.031582039318031156f,
   0.0005538422009938016f,0.004777257511010651f,-0.00107730108499558f };

// RHI[t] = (-1)^t * H[11-t]
__device__ constexpr float c_hi[12] = {
  -0.00107730108499558f, -0.004777257511010651f, 0.0005538422009938016f,
   0.031582039318031156f, 0.02752286553001629f, -0.09750160558707936f,
  -0.12976686756709563f,  0.22626469396516913f,  0.3152503517092432f,
  -0.7511339080215775f,   0.4946238903983854f,  -0.11154074335008017f };

// ---- packed f32x2 helpers (double = carrier for 2x f32 lanes) --------------
__device__ __forceinline__ double ffma2(double a, double b, double c) {
    double r;
    asm("fma.rn.f32x2 %0, %1, %2, %3;" : "=d"(r) : "d"(a), "d"(b), "d"(c));
    return r;
}
__device__ __forceinline__ double fpack(float x, float y) {   // lane0=x, lane1=y
    return __hiloint2double(__float_as_int(y), __float_as_int(x));
}
__device__ __forceinline__ float flo(double d) { return __int_as_float(__double2loint(d)); }
__device__ __forceinline__ float fhi(double d) { return __int_as_float(__double2hiint(d)); }
__device__ __forceinline__ double fdup(float x) { return fpack(x, x); }

// ---------------- scratch (static device memory) ----------------------------
__device__ float  g_ll1[17572864];   // fwd ll1 (256*261*261) | inv ll262 (256*262*262)
__device__ float  g_ll2[ 4734976];
__device__ float  g_ll3[ 1401856];   // fwd ll3 | inv ll74
__device__ float  g_ll4[  451584];
__device__ float  g_hl1[17438976];   // hl band planes (scalar)
__device__ float  g_hl2[ 4734976];
__device__ float  g_hl3[ 1364224];
__device__ float  g_hl4[  451584];
__device__ double g_bd1[17438976];   // (lh,hh) interleaved pair planes
__device__ double g_bd2[ 4734976];
__device__ double g_bd3[ 1364224];
__device__ double g_bd4[  451584];
__device__ float  g_mll4[ 451584];   // mixed ll4
__device__ float  g_mhl4[ 451584];   // mixed hl4
__device__ double g_mbd4[ 451584];   // mixed (lh,hh)

// ================= fused forward level ======================================
// in: (B,N,N) dense. out: ll,hl scalar planes + bd=(lh,hh) pair plane, (B,o,o)
#define OT   32
#define IT   74         // 2*OT+10
#define DUPP 74         // s_dup pitch (doubles)
#define LHP2 33         // s_lh pitch (doubles)
// dynamic smem: s_dup (74x74 doubles) + s_lh (74x33 doubles)
#define SMEM_FD ((IT * DUPP + IT * LHP2) * 8)

__global__ __launch_bounds__(256, 2) void fdwt2(
    const float* __restrict__ in, int N,
    float* __restrict__ ll, float* __restrict__ hl,
    double* __restrict__ bd, int o, int tilesX)
{
    extern __shared__ double sbuf[];
    double* s_dup = sbuf;                 // dup'd input tile
    double* s_lh  = sbuf + IT * DUPP;     // interleaved (lo,hi)

    int img = blockIdx.y;
    int ty = blockIdx.x / tilesX, tx = blockIdx.x % tilesX;
    int r0 = ty * OT, c0 = tx * OT;
    int tid  = threadIdx.x;
    int lane = tid & 31, wid = tid >> 5;
    const float* ip = in + (size_t)img * N * N;
    int rbase = 2 * r0 - 10, cbase = 2 * c0 - 10;

    // ---- stage A: load 74x74 input tile, store duplicated (v,v) ----
    bool interior = (rbase >= 0) && (rbase + IT <= N) && (cbase >= 0) && (cbase + IT <= N);
    if (interior && ((N & 1) == 0)) {
        // cbase always even; N even -> float2 loads aligned
        for (int i = wid; i < IT; i += 8) {
            const float2* src = reinterpret_cast<const float2*>(ip + (size_t)(rbase + i) * N + cbase);
            double* dst = &s_dup[i * DUPP];
            {
                float2 v = __ldg(src + lane);
                dst[2 * lane] = fdup(v.x); dst[2 * lane + 1] = fdup(v.y);
            }
            if (lane < 5) {
                float2 v = __ldg(src + 32 + lane);
                dst[64 + 2 * lane] = fdup(v.x); dst[64 + 2 * lane + 1] = fdup(v.y);
            }
        }
    } else if (interior) {
        for (int i = wid; i < IT; i += 8) {
            const float* src = ip + (size_t)(rbase + i) * N + cbase;
            double* dst = &s_dup[i * DUPP];
            dst[lane]      = fdup(__ldg(src + lane));
            dst[lane + 32] = fdup(__ldg(src + lane + 32));
            if (lane < 10) dst[lane + 64] = fdup(__ldg(src + lane + 64));
        }
    } else {
        for (int t = tid; t < IT * IT; t += 256) {
            int j = t % IT, i = t / IT;
            int s = rbase + i; if (s < 0) s = -1 - s; if (s >= N) s = 2 * N - 1 - s;
            int u = cbase + j; if (u < 0) u = -1 - u; if (u >= N) u = 2 * N - 1 - u;
            s_dup[i * DUPP + j] = fdup(__ldg(ip + (size_t)s * N + u));
        }
    }
    __syncthreads();

    // ---- stage B: width analysis, packed (lo,hi) accumulators, zero movs ----
    {
        double clh[12];
#pragma unroll
        for (int j = 0; j < 12; ++j) clh[j] = fpack(c_lo[j], c_hi[j]);

        int c4 = tid & 7;          // output cols 4*c4 .. 4*c4+3
        int i0 = tid >> 3;         // rows i0, i0+32, i0+64
        for (int i = i0; i < IT; i += 32) {
            const double* dp = &s_dup[i * DUPP + 8 * c4];   // taps 8c4 + (2k+t)
            double w[18];
#pragma unroll
            for (int t = 0; t < 18; ++t) w[t] = dp[t];
#pragma unroll
            for (int k = 0; k < 4; ++k) {
                double acc = 0.0;
#pragma unroll
                for (int t = 0; t < 12; ++t)
                    acc = ffma2(w[2 * k + t], clh[t], acc);
                s_lh[i * LHP2 + 4 * c4 + k] = acc;
            }
        }
    }
    __syncthreads();

    // ---- stage C: height analysis, (vl,vh) pairs x resident dup'd coeffs ----
    {
        double dlo[12], dhi[12];
#pragma unroll
        for (int j = 0; j < 12; ++j) { dlo[j] = fdup(c_lo[j]); dhi[j] = fdup(c_hi[j]); }

        int c  = tid & 31;
        int rg = tid >> 5;         // output rows 4*rg .. 4*rg+3
        double acc[8];             // per row q: (ll,hl) and (lh,hh)
#pragma unroll
        for (int q = 0; q < 8; ++q) acc[q] = 0.0;
#pragma unroll
        for (int k = 0; k < 18; ++k) {
            double v = s_lh[(8 * rg + k) * LHP2 + c];
#pragma unroll
            for (int q = 0; q < 4; ++q) {
                int t = k - 2 * q;
                if (t >= 0 && t < 12) {
                    acc[2 * q]     = ffma2(v, dlo[t], acc[2 * q]);
                    acc[2 * q + 1] = ffma2(v, dhi[t], acc[2 * q + 1]);
                }
            }
        }
        int gc = c0 + c;
        if (gc < o) {
#pragma unroll
            for (int q = 0; q < 4; ++q) {
                int gr = r0 + 4 * rg + q;
                if (gr < o) {
                    size_t oo = (size_t)img * o * o + (size_t)gr * o + gc;
                    ll[oo] = flo(acc[2 * q]);
                    hl[oo] = fhi(acc[2 * q]);
                    bd[oo] = acc[2 * q + 1];          // (lh,hh) STG.64
                }
            }
        }
    }
}

// ================= fused inverse level ======================================
// ll pitched scalar; hl scalar plane; bd=(lh,hh) pair plane (dense NxN).
// out: (B,On,On) dense, On = 2N-10.
#define OS   64
#define JS   37         // band tile span = OS/2 + 5
#define JSP2 37         // smem pitch (doubles)

__global__ __launch_bounds__(256, 2) void idwt2(
    const float* __restrict__ ll, int llp, size_t llis,
    const float* __restrict__ hl, const double* __restrict__ bd, size_t bis,
    float* __restrict__ out, int On, int N, int tilesX)
{
    __shared__ double s_ab[JS * JSP2];     // (ll, lh)
    __shared__ double s_cd[JS * JSP2];     // (hl, hh)
    __shared__ double s_lohi[OS * JSP2];   // (lo, hi) after height synth

    int img = blockIdx.y;
    int ty = blockIdx.x / tilesX, tx = blockIdx.x % tilesX;
    int r0 = ty * OS, c0 = tx * OS;
    int jr0 = r0 >> 1, jc0 = c0 >> 1;
    int tid = threadIdx.x;
    const float*  pll = ll + (size_t)img * llis;
    const float*  phl = hl + (size_t)img * bis;
    const double* pbd = bd + (size_t)img * bis;

    // ---- stage A: assemble (ll,lh) and (hl,hh) pair tiles ----
    for (int t = tid; t < JS * JS; t += 256) {
        int j = t % JS, i = t / JS;
        int jr = jr0 + i; if (jr > N - 1) jr = N - 1;
        int jc = jc0 + j; if (jc > N - 1) jc = N - 1;
        float  vll = __ldg(pll + (size_t)jr * llp + jc);
        size_t bo  = (size_t)jr * N + jc;
        float  vhl = __ldg(phl + bo);
        double vbd = __ldg(pbd + bo);      // (lh, hh)
        s_ab[i * JSP2 + j] = fpack(vll, flo(vbd));
        s_cd[i * JSP2 + j] = fpack(vhl, fhi(vbd));
    }
    __syncthreads();

    // ---- stage B: height synthesis (dot-trick), emit (lo,hi) pairs ----
    {
        double clh[12];
#pragma unroll
        for (int j = 0; j < 12; ++j) clh[j] = fpack(c_lo[j], c_hi[j]);

        for (int t = tid; t < 16 * JS; t += 256) {
            int j  = t % JS;
            int mg = t / JS;
            double ab[7], cd[7];
#pragma unroll
            for (int k = 0; k < 7; ++k) {
                int rr = (2 * mg + k) * JSP2 + j;
                ab[k] = s_ab[rr]; cd[k] = s_cd[rr];
            }
#pragma unroll
            for (int q = 0; q < 2; ++q) {
                double aE = 0.0, aO = 0.0, cE = 0.0, cO = 0.0;
#pragma unroll
                for (int k = 0; k < 6; ++k) {
                    aE = ffma2(ab[q + k], clh[10 - 2 * k], aE);
                    aO = ffma2(ab[q + k], clh[11 - 2 * k], aO);
                    cE = ffma2(cd[q + k], clh[10 - 2 * k], cE);
                    cO = ffma2(cd[q + k], clh[11 - 2 * k], cO);
                }
                float le = flo(aE) + fhi(aE), he = flo(cE) + fhi(cE);
                float lo_ = flo(aO) + fhi(aO), ho = flo(cO) + fhi(cO);
                int orow = 4 * mg + 2 * q;
                s_lohi[orow * JSP2 + j]       = fpack(le,  he);
                s_lohi[(orow + 1) * JSP2 + j] = fpack(lo_, ho);
            }
        }
    }
    __syncthreads();

    // ---- stage C: width synthesis (dot-trick), float2 stores ----
    {
        double clh[12];
#pragma unroll
        for (int j = 0; j < 12; ++j) clh[j] = fpack(c_lo[j], c_hi[j]);

        float* po = out + (size_t)img * On * On;
        int g   = tid & 15;        // output cols 4g..4g+3
        int rr0 = tid >> 4;
        for (int r = rr0; r < OS; r += 16) {
            double p[7];
#pragma unroll
            for (int k = 0; k < 7; ++k) p[k] = s_lohi[r * JSP2 + 2 * g + k];
            int gr = r0 + r;
            if (gr < On) {
#pragma unroll
                for (int q = 0; q < 2; ++q) {
                    int gc = c0 + 4 * g + 2 * q;
                    if (gc < On) {
                        double aE = 0.0, aO = 0.0;
#pragma unroll
                        for (int k = 0; k < 6; ++k) {
                            aE = ffma2(p[q + k], clh[10 - 2 * k], aE);
                            aO = ffma2(p[q + k], clh[11 - 2 * k], aO);
                        }
                        float se = flo(aE) + fhi(aE);
                        float so = flo(aO) + fhi(aO);
                        *reinterpret_cast<float2*>(po + (size_t)gr * On + gc) = make_float2(se, so);
                    }
                }
            }
        }
    }
}

// ================= channel mixing (one launch, grid.z selects plane) ========
#define PT 128
__global__ __launch_bounds__(256) void mix_all(
    const float* __restrict__ ll4, const float* __restrict__ hl4,
    const double* __restrict__ bd4,
    const float* __restrict__ wyl, const float* __restrict__ wyh,
    float* __restrict__ mll, float* __restrict__ mhl, double* __restrict__ mbd)
{
    const int P = 1764;
    __shared__ double s_buf[32 * PT];      // reused as float for scalar planes
    int pt  = blockIdx.x;
    int b   = blockIdx.y;
    int z   = blockIdx.z;                  // 0: ll, 1: hl, 2: (lh,hh) pair
    int p0  = pt * PT;
    int tid = threadIdx.x;

    if (z < 2) {
        const float* in  = (z == 0) ? ll4 : hl4;
        const float* w   = (z == 0) ? wyl : wyh;
        int ws  = (z == 0) ? 1 : 3;
        int off = (z == 0) ? 0 : 1;
        float* outp = (z == 0) ? mll : mhl;
        float* s_in = reinterpret_cast<float*>(s_buf);
        for (int t = tid; t < 32 * PT; t += 256) {
            int p = t % PT, i = t / PT;
            s_in[t] = (p0 + p < P) ? __ldg(in + (size_t)(b * 32 + i) * P + p0 + p) : 0.f;
        }
        __syncthreads();
        for (int t = tid; t < 32 * PT; t += 256) {
            int p = t % PT, o = t / PT;
            if (p0 + p < P) {
                float s = 0.f;
#pragma unroll 8
                for (int i = 0; i < 32; ++i)
                    s = fmaf(s_in[i * PT + p],
                             __ldg(w + ((size_t)(i * 32 + o) * ws + off) * P + p0 + p), s);
                outp[(size_t)(b * 32 + o) * P + p0 + p] = s;
            }
        }
    } else {
        for (int t = tid; t < 32 * PT; t += 256) {
            int p = t % PT, i = t / PT;
            s_buf[t] = (p0 + p < P) ? __ldg(bd4 + (size_t)(b * 32 + i) * P + p0 + p) : 0.0;
        }
        __syncthreads();
        for (int t = tid; t < 32 * PT; t += 256) {
            int p = t % PT, o = t / PT;
            if (p0 + p < P) {
                double acc = 0.0;
#pragma unroll 8
                for (int i = 0; i < 32; ++i) {
                    size_t wb = ((size_t)(i * 32 + o) * 3) * P + p0 + p;
                    double wp = fpack(__ldg(wyh + wb), __ldg(wyh + wb + 2 * P));
                    acc = ffma2(s_buf[i * PT + p], wp, acc);
                }
                mbd[(size_t)(b * 32 + o) * P + p0 + p] = acc;
            }
        }
    }
}

// ---------------------------------------------------------------------------
extern "C" void kernel_launch(void* const* d_in, const int* in_sizes, int n_in,
                              void* d_out, int out_size)
{
    (void)in_sizes; (void)n_in; (void)out_size;
    const float* x   = (const float*)d_in[0];
    const float* wyl = (const float*)d_in[1];
    const float* wyh = (const float*)d_in[2];
    float* out = (float*)d_out;

    float  *ll1, *ll2, *ll3, *ll4, *hl1, *hl2, *hl3, *hl4, *mll4, *mhl4;
    double *bd1, *bd2, *bd3, *bd4, *mbd4;
    cudaGetSymbolAddress((void**)&ll1, g_ll1);
    cudaGetSymbolAddress((void**)&ll2, g_ll2);
    cudaGetSymbolAddress((void**)&ll3, g_ll3);
    cudaGetSymbolAddress((void**)&ll4, g_ll4);
    cudaGetSymbolAddress((void**)&hl1, g_hl1);
    cudaGetSymbolAddress((void**)&hl2, g_hl2);
    cudaGetSymbolAddress((void**)&hl3, g_hl3);
    cudaGetSymbolAddress((void**)&hl4, g_hl4);
    cudaGetSymbolAddress((void**)&bd1, g_bd1);
    cudaGetSymbolAddress((void**)&bd2, g_bd2);
    cudaGetSymbolAddress((void**)&bd3, g_bd3);
    cudaGetSymbolAddress((void**)&bd4, g_bd4);
    cudaGetSymbolAddress((void**)&mll4, g_mll4);
    cudaGetSymbolAddress((void**)&mhl4, g_mhl4);
    cudaGetSymbolAddress((void**)&mbd4, g_mbd4);

    cudaFuncSetAttribute(fdwt2, cudaFuncAttributeMaxDynamicSharedMemorySize, SMEM_FD);

    const int B = 256;

    // ---------------- forward DWT ------------------------------------------
    fdwt2<<<dim3(9 * 9, B), 256, SMEM_FD>>>(x,   512, ll1, hl1, bd1, 261, 9);
    fdwt2<<<dim3(5 * 5, B), 256, SMEM_FD>>>(ll1, 261, ll2, hl2, bd2, 136, 5);
    fdwt2<<<dim3(3 * 3, B), 256, SMEM_FD>>>(ll2, 136, ll3, hl3, bd3,  73, 3);
    fdwt2<<<dim3(2 * 2, B), 256, SMEM_FD>>>(ll3,  73, ll4, hl4, bd4,  42, 2);

    // ---------------- channel mix (one launch) -----------------------------
    mix_all<<<dim3(14, 8, 3), 256>>>(ll4, hl4, bd4, wyl, wyh, mll4, mhl4, mbd4);

    // ---------------- inverse DWT ------------------------------------------
    // L4: 42 -> 74  (ll74 into g_ll3, dense 74)
    idwt2<<<dim3(2 * 2, B), 256>>>(mll4, 42, 1764, mhl4, mbd4, 1764,
                                   ll3, 74, 42, 2);
    // L3: ll74 crop->73; 73 -> 136 (ll136 into g_ll2)
    idwt2<<<dim3(3 * 3, B), 256>>>(ll3, 74, 5476, hl3, bd3, 5329,
                                   ll2, 136, 73, 3);
    // L2: 136 -> 262 (ll262 into g_ll1)
    idwt2<<<dim3(5 * 5, B), 256>>>(ll2, 136, 18496, hl2, bd2, 18496,
                                   ll1, 262, 136, 5);
    // L1: ll262 crop->261; 261 -> 512 -> d_out
    idwt2<<<dim3(8 * 8, B), 256>>>(ll1, 262, 68644, hl1, bd1, 68121,
                                   out, 512, 261, 8);
}

// round 12
// speedup vs baseline: 1.4206x; 1.4206x over previous
#include <cuda_runtime.h>
#include <cuda_fp16.h>

// ---------------------------------------------------------------------------
// WaveConv2d: 4-level db6 DWT -> per-pixel 32x32 channel mix at coarsest level
//             -> 4-level inverse DWT.  Compute fp32; level-1..3 band planes
//             stored fp16 (one quantization round-trip, lowpass chain fp32).
//
// R10: revert to R8 DWT kernels (42KB static smem, occ ~47%); keep merged
//      mix launch; fp16 band planes for levels 1-3 (~270MB traffic cut).
// ---------------------------------------------------------------------------

#define DIV_UP(a,b) (((a)+(b)-1)/(b))

__device__ constexpr float c_lo[12] = {
   0.11154074335008017f,  0.4946238903983854f,   0.7511339080215775f,
   0.3152503517092432f,  -0.22626469396516913f, -0.12976686756709563f,
   0.09750160558707936f,  0.02752286553001629f, -0.031582039318031156f,
   0.0005538422009938016f,0.004777257511010651f,-0.00107730108499558f };

// RHI[t] = (-1)^t * H[11-t]
__device__ constexpr float c_hi[12] = {
  -0.00107730108499558f, -0.004777257511010651f, 0.0005538422009938016f,
   0.031582039318031156f, 0.02752286553001629f, -0.09750160558707936f,
  -0.12976686756709563f,  0.22626469396516913f,  0.3152503517092432f,
  -0.7511339080215775f,   0.4946238903983854f,  -0.11154074335008017f };

// ---- packed f32x2 helpers (double = carrier for 2x f32 lanes) --------------
__device__ __forceinline__ double ffma2(double a, double b, double c) {
    double r;
    asm("fma.rn.f32x2 %0, %1, %2, %3;" : "=d"(r) : "d"(a), "d"(b), "d"(c));
    return r;
}
__device__ __forceinline__ double fpack(float x, float y) {   // lane0=x, lane1=y
    return __hiloint2double(__float_as_int(y), __float_as_int(x));
}
__device__ __forceinline__ float flo(double d) { return __int_as_float(__double2loint(d)); }
__device__ __forceinline__ float fhi(double d) { return __int_as_float(__double2hiint(d)); }
__device__ __forceinline__ double fdup(float x) { return fpack(x, x); }

// ---- typed band plane store/load helpers -----------------------------------
__device__ __forceinline__ void store_h(float* p, float v)  { *p = v; }
__device__ __forceinline__ void store_h(__half* p, float v) { *p = __float2half_rn(v); }
__device__ __forceinline__ void store_b(double* p, double v)  { *p = v; }
__device__ __forceinline__ void store_b(__half2* p, double v) {
    *p = __floats2half2_rn(flo(v), fhi(v));
}
__device__ __forceinline__ float  load_h(const float* p)  { return __ldg(p); }
__device__ __forceinline__ float  load_h(const __half* p) { return __half2float(__ldg(p)); }
__device__ __forceinline__ double load_b(const double* p) { return __ldg(p); }
__device__ __forceinline__ double load_b(const __half2* p) {
    float2 f = __half22float2(__ldg(p));
    return fpack(f.x, f.y);
}

// ---------------- scratch (static device memory) ----------------------------
__device__ float   g_ll1[17572864];   // fwd ll1 (256*261*261) | inv ll262 (256*262*262)
__device__ float   g_ll2[ 4734976];
__device__ float   g_ll3[ 1401856];   // fwd ll3 | inv ll74
__device__ float   g_ll4[  451584];
__device__ __half  g_hl1[17438976];   // hl band planes, levels 1-3 fp16
__device__ __half  g_hl2[ 4734976];
__device__ __half  g_hl3[ 1364224];
__device__ float   g_hl4[  451584];   // level 4 fp32 (goes through mix)
__device__ __half2 g_bd1[17438976];   // (lh,hh) pair planes, levels 1-3 fp16x2
__device__ __half2 g_bd2[ 4734976];
__device__ __half2 g_bd3[ 1364224];
__device__ double  g_bd4[  451584];   // level 4 pair plane (f32x2 carrier)
__device__ float   g_mll4[ 451584];   // mixed ll4
__device__ float   g_mhl4[ 451584];   // mixed hl4
__device__ double  g_mbd4[ 451584];   // mixed (lh,hh)

// ================= fused forward level ======================================
// in: (B,N,N) dense. out: ll scalar + hl scalar + bd=(lh,hh) pair, (B,o,o)
#define OT   32
#define IT   74         // 2*OT+10
#define ITP  76         // s_in pitch (floats, even)
#define LHP2 33         // s_lh pitch (doubles)

template <typename HT, typename BT>
__global__ __launch_bounds__(256) void fdwt2(
    const float* __restrict__ in, int N,
    float* __restrict__ ll, HT* __restrict__ hl,
    BT* __restrict__ bd, int o, int tilesX)
{
    __shared__ float  s_in[IT * ITP];
    __shared__ double s_lh[IT * LHP2];     // interleaved (lo,hi)

    int img = blockIdx.y;
    int ty = blockIdx.x / tilesX, tx = blockIdx.x % tilesX;
    int r0 = ty * OT, c0 = tx * OT;
    int tid  = threadIdx.x;
    int lane = tid & 31, wid = tid >> 5;
    const float* ip = in + (size_t)img * N * N;
    int rbase = 2 * r0 - 10, cbase = 2 * c0 - 10;

    // ---- stage A: load 74x74 input tile ----
    bool interior = (rbase >= 0) && (rbase + IT <= N) && (cbase >= 0) && (cbase + IT <= N);
    if (interior && ((N & 1) == 0)) {
        for (int i = wid; i < IT; i += 8) {
            const float2* src = reinterpret_cast<const float2*>(ip + (size_t)(rbase + i) * N + cbase);
            float2* dst = reinterpret_cast<float2*>(&s_in[i * ITP]);
            dst[lane] = __ldg(src + lane);
            if (lane < 5) dst[32 + lane] = __ldg(src + 32 + lane);
        }
    } else if (interior) {
        for (int i = wid; i < IT; i += 8) {
            const float* src = ip + (size_t)(rbase + i) * N + cbase;
            float* dst = &s_in[i * ITP];
            dst[lane]      = __ldg(src + lane);
            dst[lane + 32] = __ldg(src + lane + 32);
            if (lane < 10) dst[lane + 64] = __ldg(src + lane + 64);
        }
    } else {
        for (int t = tid; t < IT * IT; t += 256) {
            int j = t % IT, i = t / IT;
            int s = rbase + i; if (s < 0) s = -1 - s; if (s >= N) s = 2 * N - 1 - s;
            int u = cbase + j; if (u < 0) u = -1 - u; if (u >= N) u = 2 * N - 1 - u;
            s_in[i * ITP + j] = __ldg(ip + (size_t)s * N + u);
        }
    }
    __syncthreads();

    // ---- stage B: width analysis, packed (lo,hi) accumulators ----
    {
        double clh[12];
#pragma unroll
        for (int j = 0; j < 12; ++j) clh[j] = fpack(c_lo[j], c_hi[j]);

        int c4 = tid & 7;          // cols 4*c4 .. 4*c4+3
        int i0 = tid >> 3;         // rows i0, i0+32, i0+64
        for (int i = i0; i < IT; i += 32) {
            const double* p = reinterpret_cast<const double*>(&s_in[i * ITP + 8 * c4]);
            double dw[18];
#pragma unroll
            for (int q = 0; q < 9; ++q) {
                double v = p[q];
                dw[2 * q]     = fdup(flo(v));
                dw[2 * q + 1] = fdup(fhi(v));
            }
#pragma unroll
            for (int k = 0; k < 4; ++k) {
                double acc = 0.0;
#pragma unroll
                for (int t = 0; t < 12; ++t)
                    acc = ffma2(dw[2 * k + t], clh[t], acc);
                s_lh[i * LHP2 + 4 * c4 + k] = acc;
            }
        }
    }
    __syncthreads();

    // ---- stage C: height analysis, data pairs (vl,vh) x dup'd coeffs ----
    {
        double dlo[12], dhi[12];
#pragma unroll
        for (int j = 0; j < 12; ++j) { dlo[j] = fdup(c_lo[j]); dhi[j] = fdup(c_hi[j]); }

        int c  = tid & 31;
        int rg = tid >> 5;         // output rows 4*rg .. 4*rg+3
        double acc[8];             // per row q: (ll,hl) and (lh,hh)
#pragma unroll
        for (int q = 0; q < 8; ++q) acc[q] = 0.0;
#pragma unroll
        for (int k = 0; k < 18; ++k) {
            double v = s_lh[(8 * rg + k) * LHP2 + c];
#pragma unroll
            for (int q = 0; q < 4; ++q) {
                int t = k - 2 * q;
                if (t >= 0 && t < 12) {
                    acc[2 * q]     = ffma2(v, dlo[t], acc[2 * q]);
                    acc[2 * q + 1] = ffma2(v, dhi[t], acc[2 * q + 1]);
                }
            }
        }
        int gc = c0 + c;
        if (gc < o) {
#pragma unroll
            for (int q = 0; q < 4; ++q) {
                int gr = r0 + 4 * rg + q;
                if (gr < o) {
                    size_t oo = (size_t)img * o * o + (size_t)gr * o + gc;
                    ll[oo] = flo(acc[2 * q]);
                    store_h(hl + oo, fhi(acc[2 * q]));
                    store_b(bd + oo, acc[2 * q + 1]);     // (lh,hh)
                }
            }
        }
    }
}

// ================= fused inverse level ======================================
// ll pitched scalar; hl scalar plane; bd=(lh,hh) pair plane (dense NxN).
// out: (B,On,On) dense, On = 2N-10.
#define OS   64
#define JS   37         // band tile span = OS/2 + 5
#define JSP2 37         // smem pitch (doubles)

template <typename HT, typename BT>
__global__ __launch_bounds__(256) void idwt2(
    const float* __restrict__ ll, int llp, size_t llis,
    const HT* __restrict__ hl, const BT* __restrict__ bd, size_t bis,
    float* __restrict__ out, int On, int N, int tilesX)
{
    __shared__ double s_ab[JS * JSP2];     // (ll, lh)
    __shared__ double s_cd[JS * JSP2];     // (hl, hh)
    __shared__ double s_lohi[OS * JSP2];   // (lo, hi) after height synth

    int img = blockIdx.y;
    int ty = blockIdx.x / tilesX, tx = blockIdx.x % tilesX;
    int r0 = ty * OS, c0 = tx * OS;
    int jr0 = r0 >> 1, jc0 = c0 >> 1;
    int tid = threadIdx.x;
    const float* pll = ll + (size_t)img * llis;
    const HT*    phl = hl + (size_t)img * bis;
    const BT*    pbd = bd + (size_t)img * bis;

    // ---- stage A: assemble (ll,lh) and (hl,hh) pair tiles ----
    for (int t = tid; t < JS * JS; t += 256) {
        int j = t % JS, i = t / JS;
        int jr = jr0 + i; if (jr > N - 1) jr = N - 1;
        int jc = jc0 + j; if (jc > N - 1) jc = N - 1;
        float  vll = __ldg(pll + (size_t)jr * llp + jc);
        size_t bo  = (size_t)jr * N + jc;
        float  vhl = load_h(phl + bo);
        double vbd = load_b(pbd + bo);     // (lh, hh)
        s_ab[i * JSP2 + j] = fpack(vll, flo(vbd));
        s_cd[i * JSP2 + j] = fpack(vhl, fhi(vbd));
    }
    __syncthreads();

    // ---- stage B: height synthesis (dot-trick), emit (lo,hi) pairs ----
    {
        double clh[12];
#pragma unroll
        for (int j = 0; j < 12; ++j) clh[j] = fpack(c_lo[j], c_hi[j]);

        for (int t = tid; t < 16 * JS; t += 256) {
            int j  = t % JS;
            int mg = t / JS;
            double ab[7], cd[7];
#pragma unroll
            for (int k = 0; k < 7; ++k) {
                int rr = (2 * mg + k) * JSP2 + j;
                ab[k] = s_ab[rr]; cd[k] = s_cd[rr];
            }
#pragma unroll
            for (int q = 0; q < 2; ++q) {
                double aE = 0.0, aO = 0.0, cE = 0.0, cO = 0.0;
#pragma unroll
                for (int k = 0; k < 6; ++k) {
                    aE = ffma2(ab[q + k], clh[10 - 2 * k], aE);
                    aO = ffma2(ab[q + k], clh[11 - 2 * k], aO);
                    cE = ffma2(cd[q + k], clh[10 - 2 * k], cE);
                    cO = ffma2(cd[q + k], clh[11 - 2 * k], cO);
                }
                float le = flo(aE) + fhi(aE), he = flo(cE) + fhi(cE);
                float lo_ = flo(aO) + fhi(aO), ho = flo(cO) + fhi(cO);
                int orow = 4 * mg + 2 * q;
                s_lohi[orow * JSP2 + j]       = fpack(le,  he);
                s_lohi[(orow + 1) * JSP2 + j] = fpack(lo_, ho);
            }
        }
    }
    __syncthreads();

    // ---- stage C: width synthesis (dot-trick), float2 stores ----
    {
        double clh[12];
#pragma unroll
        for (int j = 0; j < 12; ++j) clh[j] = fpack(c_lo[j], c_hi[j]);

        float* po = out + (size_t)img * On * On;
        int g   = tid & 15;        // output cols 4g..4g+3
        int rr0 = tid >> 4;
        for (int r = rr0; r < OS; r += 16) {
            double p[7];
#pragma unroll
            for (int k = 0; k < 7; ++k) p[k] = s_lohi[r * JSP2 + 2 * g + k];
            int gr = r0 + r;
            if (gr < On) {
#pragma unroll
                for (int q = 0; q < 2; ++q) {
                    int gc = c0 + 4 * g + 2 * q;
                    if (gc < On) {
                        double aE = 0.0, aO = 0.0;
#pragma unroll
                        for (int k = 0; k < 6; ++k) {
                            aE = ffma2(p[q + k], clh[10 - 2 * k], aE);
                            aO = ffma2(p[q + k], clh[11 - 2 * k], aO);
                        }
                        float se = flo(aE) + fhi(aE);
                        float so = flo(aO) + fhi(aO);
                        *reinterpret_cast<float2*>(po + (size_t)gr * On + gc) = make_float2(se, so);
                    }
                }
            }
        }
    }
}

// ================= channel mixing (one launch, grid.z selects plane) ========
#define PT 128
__global__ __launch_bounds__(256) void mix_all(
    const float* __restrict__ ll4, const float* __restrict__ hl4,
    const double* __restrict__ bd4,
    const float* __restrict__ wyl, const float* __restrict__ wyh,
    float* __restrict__ mll, float* __restrict__ mhl, double* __restrict__ mbd)
{
    const int P = 1764;
    __shared__ double s_buf[32 * PT];
    int pt  = blockIdx.x;
    int b   = blockIdx.y;
    int z   = blockIdx.z;                  // 0: ll, 1: hl, 2: (lh,hh) pair
    int p0  = pt * PT;
    int tid = threadIdx.x;

    if (z < 2) {
        const float* in  = (z == 0) ? ll4 : hl4;
        const float* w   = (z == 0) ? wyl : wyh;
        int ws  = (z == 0) ? 1 : 3;
        int off = (z == 0) ? 0 : 1;
        float* outp = (z == 0) ? mll : mhl;
        float* s_in = reinterpret_cast<float*>(s_buf);
        for (int t = tid; t < 32 * PT; t += 256) {
            int p = t % PT, i = t / PT;
            s_in[t] = (p0 + p < P) ? __ldg(in + (size_t)(b * 32 + i) * P + p0 + p) : 0.f;
        }
        __syncthreads();
        for (int t = tid; t < 32 * PT; t += 256) {
            int p = t % PT, o = t / PT;
            if (p0 + p < P) {
                float s = 0.f;
#pragma unroll 8
                for (int i = 0; i < 32; ++i)
                    s = fmaf(s_in[i * PT + p],
                             __ldg(w + ((size_t)(i * 32 + o) * ws + off) * P + p0 + p), s);
                outp[(size_t)(b * 32 + o) * P + p0 + p] = s;
            }
        }
    } else {
        for (int t = tid; t < 32 * PT; t += 256) {
            int p = t % PT, i = t / PT;
            s_buf[t] = (p0 + p < P) ? __ldg(bd4 + (size_t)(b * 32 + i) * P + p0 + p) : 0.0;
        }
        __syncthreads();
        for (int t = tid; t < 32 * PT; t += 256) {
            int p = t % PT, o = t / PT;
            if (p0 + p < P) {
                double acc = 0.0;
#pragma unroll 8
                for (int i = 0; i < 32; ++i) {
                    size_t wb = ((size_t)(i * 32 + o) * 3) * P + p0 + p;
                    double wp = fpack(__ldg(wyh + wb), __ldg(wyh + wb + 2 * P));
                    acc = ffma2(s_buf[i * PT + p], wp, acc);
                }
                mbd[(size_t)(b * 32 + o) * P + p0 + p] = acc;
            }
        }
    }
}

// ---------------------------------------------------------------------------
extern "C" void kernel_launch(void* const* d_in, const int* in_sizes, int n_in,
                              void* d_out, int out_size)
{
    (void)in_sizes; (void)n_in; (void)out_size;
    const float* x   = (const float*)d_in[0];
    const float* wyl = (const float*)d_in[1];
    const float* wyh = (const float*)d_in[2];
    float* out = (float*)d_out;

    float   *ll1, *ll2, *ll3, *ll4, *hl4, *mll4, *mhl4;
    __half  *hl1, *hl2, *hl3;
    __half2 *bd1, *bd2, *bd3;
    double  *bd4, *mbd4;
    cudaGetSymbolAddress((void**)&ll1, g_ll1);
    cudaGetSymbolAddress((void**)&ll2, g_ll2);
    cudaGetSymbolAddress((void**)&ll3, g_ll3);
    cudaGetSymbolAddress((void**)&ll4, g_ll4);
    cudaGetSymbolAddress((void**)&hl1, g_hl1);
    cudaGetSymbolAddress((void**)&hl2, g_hl2);
    cudaGetSymbolAddress((void**)&hl3, g_hl3);
    cudaGetSymbolAddress((void**)&hl4, g_hl4);
    cudaGetSymbolAddress((void**)&bd1, g_bd1);
    cudaGetSymbolAddress((void**)&bd2, g_bd2);
    cudaGetSymbolAddress((void**)&bd3, g_bd3);
    cudaGetSymbolAddress((void**)&bd4, g_bd4);
    cudaGetSymbolAddress((void**)&mll4, g_mll4);
    cudaGetSymbolAddress((void**)&mhl4, g_mhl4);
    cudaGetSymbolAddress((void**)&mbd4, g_mbd4);

    const int B = 256;

    // ---------------- forward DWT ------------------------------------------
    fdwt2<__half, __half2><<<dim3(9 * 9, B), 256>>>(x,   512, ll1, hl1, bd1, 261, 9);
    fdwt2<__half, __half2><<<dim3(5 * 5, B), 256>>>(ll1, 261, ll2, hl2, bd2, 136, 5);
    fdwt2<__half, __half2><<<dim3(3 * 3, B), 256>>>(ll2, 136, ll3, hl3, bd3,  73, 3);
    fdwt2<float,  double ><<<dim3(2 * 2, B), 256>>>(ll3,  73, ll4, hl4, bd4,  42, 2);

    // ---------------- channel mix (one launch) -----------------------------
    mix_all<<<dim3(14, 8, 3), 256>>>(ll4, hl4, bd4, wyl, wyh, mll4, mhl4, mbd4);

    // ---------------- inverse DWT ------------------------------------------
    // L4: 42 -> 74  (ll74 into g_ll3, dense 74)
    idwt2<float,  double ><<<dim3(2 * 2, B), 256>>>(mll4, 42, 1764, mhl4, mbd4, 1764,
                                                    ll3, 74, 42, 2);
    // L3: ll74 crop->73; 73 -> 136 (ll136 into g_ll2)
    idwt2<__half, __half2><<<dim3(3 * 3, B), 256>>>(ll3, 74, 5476, hl3, bd3, 5329,
                                                    ll2, 136, 73, 3);
    // L2: 136 -> 262 (ll262 into g_ll1)
    idwt2<__half, __half2><<<dim3(5 * 5, B), 256>>>(ll2, 136, 18496, hl2, bd2, 18496,
                                                    ll1, 262, 136, 5);
    // L1: ll262 crop->261; 261 -> 512 -> d_out
    idwt2<__half, __half2><<<dim3(8 * 8, B), 256>>>(ll1, 262, 68644, hl1, bd1, 68121,
                                                    out, 512, 261, 8);
}